// round 2
// baseline (speedup 1.0000x reference)
#include <cuda_runtime.h>
#include <math.h>

// Problem constants
#define NB   32
#define HGc  24
#define WGc  24
#define Dc   768
#define HIDc 384
#define G4c  1536          // 4*HID
#define Tc   24
#define NSEQ 768           // NB*24  (both orientations)
#define MTOT 18432         // NSEQ*T

// Scratch (device globals — allowed; no cudaMalloc)
static __device__ float g_z[(size_t)4 * MTOT * G4c];     // z = x@Wx + b, per direction: [dir][n*T+t][1536]
static __device__ float g_h[2][4][NSEQ * HIDc];          // double-buffered hidden state
static __device__ float g_c[4][NSEQ * HIDc];             // cell state

// ---------------------------------------------------------------------------
// Zero-init h (both parities) and c
// ---------------------------------------------------------------------------
__global__ void init_state_kernel() {
    size_t i = (size_t)blockIdx.x * blockDim.x + threadIdx.x;
    const size_t n = (size_t)4 * NSEQ * HIDc;
    if (i < n) {
        ((float*)g_h)[i]     = 0.f;   // parity 0
        ((float*)g_h)[n + i] = 0.f;   // parity 1
        ((float*)g_c)[i]     = 0.f;
    }
}

// ---------------------------------------------------------------------------
// Phase 1: z[dir][m][c] = sum_k A[row(m)][k] * W[k][c] + bias[c]
// 128x128x8 register-blocked SGEMM, 256 threads, 8x8 per thread.
// N dimension = 3072 (two weight matrices side by side: fwd cols 0..1535,
// bwd cols 1536..3071). orientation 0 = horizontal (rows contiguous),
// orientation 1 = vertical (gathered rows of the feature tensor).
// ---------------------------------------------------------------------------
__global__ __launch_bounds__(256, 2)
void gemm_z_kernel(const float* __restrict__ A,
                   const float* __restrict__ W0, const float* __restrict__ W1,
                   const float* __restrict__ b0, const float* __restrict__ b1,
                   int orientation, int dirbase) {
    __shared__ float As[8][128];
    __shared__ float Bs[8][128];

    const int tid = threadIdx.x;
    const int bx  = blockIdx.x;           // col tile (0..23)
    const int by  = blockIdx.y;           // row tile (0..143)
    const int cg0 = bx * 128;             // global col in [0,3072)

    const bool second = (cg0 >= G4c);
    const float* W    = second ? W1 : W0;
    const float* bias = second ? b1 : b0;
    const int    wc0  = second ? (cg0 - G4c) : cg0;   // col within weight matrix
    const int    dir  = dirbase + (second ? 1 : 0);

    // A-tile load indices: thread loads one float4 along K from one row
    const int a_row = tid >> 1;            // 0..127
    const int a_k4  = (tid & 1) * 4;       // 0 or 4
    int m = by * 128 + a_row;
    int rf;
    if (orientation == 0) {
        rf = m;                                        // features row == m
    } else {
        int t  = m % 24;
        int nn = m / 24;
        int wg = nn % 24;
        int b  = nn / 24;
        rf = b * 576 + t * 24 + wg;                    // features[(b,t,wg)]
    }
    const float* Arow = A + (size_t)rf * Dc;

    // B-tile load indices: thread loads one float4 along N
    const int b_row = tid >> 5;            // 0..7 (k within tile)
    const int b_c4  = (tid & 31) * 4;      // 0..124

    // compute-thread mapping: 16x16 thread grid, 8x8 outputs each
    const int ty = tid >> 4;               // 0..15
    const int tx = tid & 15;               // 0..15

    float acc[8][8];
#pragma unroll
    for (int i = 0; i < 8; i++)
#pragma unroll
        for (int j = 0; j < 8; j++) acc[i][j] = 0.f;

    for (int k0 = 0; k0 < Dc; k0 += 8) {
        float4 av = *(const float4*)(Arow + k0 + a_k4);
        As[a_k4 + 0][a_row] = av.x;
        As[a_k4 + 1][a_row] = av.y;
        As[a_k4 + 2][a_row] = av.z;
        As[a_k4 + 3][a_row] = av.w;
        *(float4*)&Bs[b_row][b_c4] =
            *(const float4*)(W + (size_t)(k0 + b_row) * G4c + wc0 + b_c4);
        __syncthreads();

#pragma unroll
        for (int kk = 0; kk < 8; kk++) {
            float ar[8], br[8];
            *(float4*)&ar[0] = *(const float4*)&As[kk][ty * 8 + 0];
            *(float4*)&ar[4] = *(const float4*)&As[kk][ty * 8 + 4];
            *(float4*)&br[0] = *(const float4*)&Bs[kk][tx * 8 + 0];
            *(float4*)&br[4] = *(const float4*)&Bs[kk][tx * 8 + 4];
#pragma unroll
            for (int i = 0; i < 8; i++)
#pragma unroll
                for (int j = 0; j < 8; j++) acc[i][j] += ar[i] * br[j];
        }
        __syncthreads();
    }

    // Epilogue: add bias, store to g_z[dir]
    float* Z = g_z + (size_t)dir * MTOT * G4c;
#pragma unroll
    for (int i = 0; i < 8; i++) {
        int mm = by * 128 + ty * 8 + i;
#pragma unroll
        for (int j = 0; j < 8; j += 4) {
            int c = wc0 + tx * 8 + j;
            float4 v;
            v.x = acc[i][j + 0] + bias[c + 0];
            v.y = acc[i][j + 1] + bias[c + 1];
            v.z = acc[i][j + 2] + bias[c + 2];
            v.w = acc[i][j + 3] + bias[c + 3];
            *(float4*)&Z[(size_t)mm * G4c + c] = v;
        }
    }
}

// ---------------------------------------------------------------------------
// Phase 2: one LSTM recurrence step for all 4 directions.
// Block: 64 sequences x 32 hidden cols (x 4 gates = 128 output cols), K=384.
// g = z[t] + h_prev @ Wh ; gates ; update c ; h_new -> state + output.
// grid = (HID/32=12, NSEQ/64=12, 4 dirs), 256 threads.
// ---------------------------------------------------------------------------
__device__ __forceinline__ float sigf(float x) {
    return 1.f / (1.f + __expf(-x));
}

__global__ __launch_bounds__(256, 4)
void lstm_step_kernel(const float* __restrict__ Wh_hf, const float* __restrict__ Wh_hb,
                      const float* __restrict__ Wh_vf, const float* __restrict__ Wh_vb,
                      float* __restrict__ out, int s, int parity) {
    const int dir = blockIdx.z;
    const float* Wh = (dir == 0) ? Wh_hf : (dir == 1) ? Wh_hb : (dir == 2) ? Wh_vf : Wh_vb;
    const bool forward = (dir == 0) || (dir == 2);
    const int t = forward ? s : (Tc - 1 - s);

    const int c0 = blockIdx.x * 32;   // hidden-col tile
    const int n0 = blockIdx.y * 64;   // sequence tile

    __shared__ float hs[64][64];      // [row][k]
    __shared__ float ws[64][128];     // [k][gate*32 + j]

    const float* hprev = g_h[parity][dir];
    float*       hnext = g_h[parity ^ 1][dir];
    float*       cst   = g_c[dir];
    const float* Z     = g_z + (size_t)dir * MTOT * G4c;

    const int tid = threadIdx.x;
    const int j   = tid & 31;         // hidden col within tile
    const int rg  = tid >> 5;         // row group: rows rg*8 .. rg*8+7

    float acc[8][4];
#pragma unroll
    for (int i = 0; i < 8; i++)
#pragma unroll
        for (int g = 0; g < 4; g++) acc[i][g] = 0.f;

    for (int kt = 0; kt < HIDc; kt += 64) {
        // load h tile: 64x64 floats, float4 per thread x4
#pragma unroll
        for (int q = 0; q < 4; q++) {
            int e   = (tid + q * 256) * 4;
            int row = e >> 6;
            int col = e & 63;
            *(float4*)&hs[row][col] =
                *(const float4*)&hprev[(size_t)(n0 + row) * HIDc + kt + col];
        }
        // load Wh tile: 64 k x 128 cols (4 gates x 32)
#pragma unroll
        for (int q = 0; q < 8; q++) {
            int e  = (tid + q * 256) * 4;
            int kk = e >> 7;
            int cj = e & 127;
            int g  = cj >> 5;
            int jj = cj & 31;
            *(float4*)&ws[kk][cj] =
                *(const float4*)&Wh[(size_t)(kt + kk) * G4c + g * HIDc + c0 + jj];
        }
        __syncthreads();

#pragma unroll 16
        for (int kk = 0; kk < 64; kk++) {
            float w0 = ws[kk][j];
            float w1 = ws[kk][32 + j];
            float w2 = ws[kk][64 + j];
            float w3 = ws[kk][96 + j];
#pragma unroll
            for (int i = 0; i < 8; i++) {
                float hv = hs[rg * 8 + i][kk];
                acc[i][0] += hv * w0;
                acc[i][1] += hv * w1;
                acc[i][2] += hv * w2;
                acc[i][3] += hv * w3;
            }
        }
        __syncthreads();
    }

    // Epilogue: gates, state update, output write
    const int cidx = c0 + j;
#pragma unroll
    for (int i = 0; i < 8; i++) {
        int n = n0 + rg * 8 + i;
        size_t zb = ((size_t)n * Tc + t) * G4c + cidx;
        float gi = acc[i][0] + Z[zb];
        float gf = acc[i][1] + Z[zb + HIDc];
        float gg = acc[i][2] + Z[zb + 2 * HIDc];
        float go = acc[i][3] + Z[zb + 3 * HIDc];

        float iv = sigf(gi);
        float fv = sigf(gf);
        float cv = tanhf(gg);
        float ov = sigf(go);

        size_t sidx = (size_t)n * HIDc + cidx;
        float cn = fv * cst[sidx] + iv * cv;
        cst[sidx] = cn;
        float hn = ov * tanhf(cn);
        hnext[sidx] = hn;

        // output location
        size_t orow;
        if (dir < 2) {
            orow = (size_t)n * WGc + t;                       // (b*HG+hg)*WG + wg
        } else {
            int b  = n / WGc;
            int wg = n % WGc;
            orow = (size_t)b * (HGc * WGc) + (size_t)t * WGc + wg;
        }
        out[orow * 1536 + (size_t)dir * HIDc + cidx] = hn;
    }
}

// ---------------------------------------------------------------------------
// Launch
// ---------------------------------------------------------------------------
extern "C" void kernel_launch(void* const* d_in, const int* in_sizes, int n_in,
                              void* d_out, int out_size) {
    const float* features = (const float*)d_in[0];
    const float* hf_Wx = (const float*)d_in[1];
    const float* hf_Wh = (const float*)d_in[2];
    const float* hf_b  = (const float*)d_in[3];
    const float* hb_Wx = (const float*)d_in[4];
    const float* hb_Wh = (const float*)d_in[5];
    const float* hb_b  = (const float*)d_in[6];
    const float* vf_Wx = (const float*)d_in[7];
    const float* vf_Wh = (const float*)d_in[8];
    const float* vf_b  = (const float*)d_in[9];
    const float* vb_Wx = (const float*)d_in[10];
    const float* vb_Wh = (const float*)d_in[11];
    const float* vb_b  = (const float*)d_in[12];
    float* out = (float*)d_out;

    // zero states
    {
        size_t n = (size_t)4 * NSEQ * HIDc;
        int blocks = (int)((n + 255) / 256);
        init_state_kernel<<<blocks, 256>>>();
    }

    // Phase 1: input projections (two orientations, fwd+bwd fused on N)
    {
        dim3 grid(3072 / 128, MTOT / 128);
        gemm_z_kernel<<<grid, 256>>>(features, hf_Wx, hb_Wx, hf_b, hb_b, 0, 0);
        gemm_z_kernel<<<grid, 256>>>(features, vf_Wx, vb_Wx, vf_b, vb_b, 1, 2);
    }

    // Phase 2: 24 sequential recurrence steps (all 4 directions per launch)
    {
        dim3 grid(HIDc / 32, NSEQ / 64, 4);
        for (int s = 0; s < Tc; s++) {
            lstm_step_kernel<<<grid, 256>>>(hf_Wh, hb_Wh, vf_Wh, vb_Wh, out, s, s & 1);
        }
    }
}

// round 4
// speedup vs baseline: 3.1134x; 3.1134x over previous
#include <cuda_runtime.h>
#include <math.h>
#include <stdint.h>

// Problem constants
#define NB   32
#define HGc  24
#define WGc  24
#define Dc   768
#define HIDc 384
#define G4c  1536          // 4*HID
#define Tc   24
#define NSEQ 768           // NB*24  (per direction)
#define MTOT 18432         // NSEQ*T

// Scratch (device globals — allowed; no cudaMalloc)
static __device__ float g_z[(size_t)4 * MTOT * G4c];     // z = x@Wx + b  [dir][n*T+t][1536]
static __device__ float g_h[2][4][NSEQ * HIDc];          // double-buffered hidden state
static __device__ float g_c[4][NSEQ * HIDc];             // cell state

// ---------------------------------------------------------------------------
// Helpers: tf32 convert + warp mma (base sm_103 features, no tcgen05)
// ---------------------------------------------------------------------------
__device__ __forceinline__ uint32_t f2tf32(float f) {
    uint32_t r;
    asm("cvt.rna.tf32.f32 %0, %1;" : "=r"(r) : "f"(f));
    return r;
}

__device__ __forceinline__ void mma_tf32(float (&c)[4],
                                         const uint32_t (&a)[4],
                                         uint32_t b0, uint32_t b1) {
    asm volatile(
        "mma.sync.aligned.m16n8k8.row.col.f32.tf32.tf32.f32 "
        "{%0,%1,%2,%3}, {%4,%5,%6,%7}, {%8,%9}, {%0,%1,%2,%3};"
        : "+f"(c[0]), "+f"(c[1]), "+f"(c[2]), "+f"(c[3])
        : "r"(a[0]), "r"(a[1]), "r"(a[2]), "r"(a[3]), "r"(b0), "r"(b1));
}

__device__ __forceinline__ float sigf(float x) {
    return 1.f / (1.f + __expf(-x));
}

// ---------------------------------------------------------------------------
// Zero-init h (both parities) and c
// ---------------------------------------------------------------------------
__global__ void init_state_kernel() {
    size_t i = (size_t)blockIdx.x * blockDim.x + threadIdx.x;
    const size_t n = (size_t)4 * NSEQ * HIDc;
    if (i < n) {
        ((float*)g_h)[i]     = 0.f;
        ((float*)g_h)[n + i] = 0.f;
        ((float*)g_c)[i]     = 0.f;
    }
}

// ---------------------------------------------------------------------------
// Phase 1: z = x @ Wx + b via mma.sync tf32.
// CTA tile 128(M) x 128(N), K=768 chunked by 32.
// 8 warps = 4(M) x 2(N); warp tile 32x64 -> 2 m16-tiles x 8 n8-tiles.
// SMEM: A[m][k] stride 36 (conflict-free frags), B[k][n] stride 136.
// grid = (24 col tiles of 3072, 144 row tiles, 2 orientations)
// ---------------------------------------------------------------------------
#define SA1 36
#define SB1 136

__global__ __launch_bounds__(256, 2)
void gemm_z_mma(const float* __restrict__ feat,
                const float* __restrict__ Whf, const float* __restrict__ Whb,
                const float* __restrict__ Wvf, const float* __restrict__ Wvb,
                const float* __restrict__ bhf, const float* __restrict__ bhb,
                const float* __restrict__ bvf, const float* __restrict__ bvb) {
    __shared__ uint32_t As[128 * SA1];
    __shared__ uint32_t Bs[32 * SB1];

    const int tid  = threadIdx.x;
    const int lane = tid & 31;
    const int wid  = tid >> 5;
    const int wm   = wid & 3;      // 0..3
    const int wn   = wid >> 2;     // 0..1

    const int bx = blockIdx.x;           // 0..23 (cols of 3072)
    const int by = blockIdx.y;           // 0..143
    const int orient = blockIdx.z;       // 0=H, 1=V

    const int gc0  = bx * 128;
    const int half = (gc0 >= G4c) ? 1 : 0;
    const int wc0  = gc0 - half * G4c;
    const int dir  = orient * 2 + half;
    const float* W    = (orient == 0) ? (half ? Whb : Whf) : (half ? Wvb : Wvf);
    const float* bias = (orient == 0) ? (half ? bhb : bhf) : (half ? bvb : bvf);
    const int m0 = by * 128;

    // Per-thread A row pointers (row gather for vertical orientation)
    const float* aptr[4];
#pragma unroll
    for (int q = 0; q < 4; q++) {
        int row = (tid >> 3) + q * 32;
        int m = m0 + row;
        int rf;
        if (orient == 0) {
            rf = m;
        } else {
            int t  = m % 24;
            int nn = m / 24;
            int wg = nn % 24;
            int b  = nn / 24;
            rf = b * 576 + t * 24 + wg;
        }
        aptr[q] = feat + (size_t)rf * Dc + (tid & 7) * 4;
    }

    float acc[2][8][4];
#pragma unroll
    for (int mt = 0; mt < 2; mt++)
#pragma unroll
        for (int nt = 0; nt < 8; nt++)
#pragma unroll
            for (int e = 0; e < 4; e++) acc[mt][nt][e] = 0.f;

    const int a_r = wm * 32 + (lane >> 2);
    const int a_c = lane & 3;
    const int b_c = wn * 64 + (lane >> 2);
    const int b_r = lane & 3;

    for (int kt = 0; kt < Dc; kt += 32) {
        // Load A tile: 128 rows x 32 k (cvt to tf32)
#pragma unroll
        for (int q = 0; q < 4; q++) {
            float4 v = *(const float4*)(aptr[q] + kt);
            uint4 u = make_uint4(f2tf32(v.x), f2tf32(v.y), f2tf32(v.z), f2tf32(v.w));
            int row = (tid >> 3) + q * 32;
            *(uint4*)&As[row * SA1 + (tid & 7) * 4] = u;
        }
        // Load B tile: 32 k x 128 n
#pragma unroll
        for (int q = 0; q < 4; q++) {
            int kk = (tid >> 5) + q * 8;
            float4 v = *(const float4*)(W + (size_t)(kt + kk) * G4c + wc0 + (tid & 31) * 4);
            uint4 u = make_uint4(f2tf32(v.x), f2tf32(v.y), f2tf32(v.z), f2tf32(v.w));
            *(uint4*)&Bs[kk * SB1 + (tid & 31) * 4] = u;
        }
        __syncthreads();

#pragma unroll
        for (int k8 = 0; k8 < 4; k8++) {
            uint32_t a[2][4];
#pragma unroll
            for (int mt = 0; mt < 2; mt++) {
                int r = a_r + mt * 16;
                int c = k8 * 8 + a_c;
                a[mt][0] = As[r * SA1 + c];
                a[mt][1] = As[(r + 8) * SA1 + c];
                a[mt][2] = As[r * SA1 + c + 4];
                a[mt][3] = As[(r + 8) * SA1 + c + 4];
            }
#pragma unroll
            for (int nt = 0; nt < 8; nt++) {
                int bc = b_c + nt * 8;
                int br = k8 * 8 + b_r;
                uint32_t b0 = Bs[br * SB1 + bc];
                uint32_t b1 = Bs[(br + 4) * SB1 + bc];
                mma_tf32(acc[0][nt], a[0], b0, b1);
                mma_tf32(acc[1][nt], a[1], b0, b1);
            }
        }
        __syncthreads();
    }

    // Epilogue: add bias, store directly
    float* Zt = g_z + (size_t)dir * MTOT * G4c;
#pragma unroll
    for (int mt = 0; mt < 2; mt++) {
        int r = m0 + wm * 32 + mt * 16 + (lane >> 2);
#pragma unroll
        for (int nt = 0; nt < 8; nt++) {
            int c = wc0 + wn * 64 + nt * 8 + 2 * (lane & 3);
            float bv0 = __ldg(&bias[c]);
            float bv1 = __ldg(&bias[c + 1]);
            float2 v0 = make_float2(acc[mt][nt][0] + bv0, acc[mt][nt][1] + bv1);
            float2 v1 = make_float2(acc[mt][nt][2] + bv0, acc[mt][nt][3] + bv1);
            *(float2*)&Zt[(size_t)r * G4c + c]       = v0;
            *(float2*)&Zt[(size_t)(r + 8) * G4c + c] = v1;
        }
    }
}

// ---------------------------------------------------------------------------
// Phase 2: one LSTM step, all 4 directions, mma.sync tf32.
// CTA: 64 seqs x 64 hidden cols (x4 gates = 256 N cols), K=384 chunked by 32.
// 8 warps = 2(M) x 4(N); warp tile 32 seqs x 16 cols -> per k8:
// 2 m16-tiles x (4 gates x 2 n8-tiles) = 16 mma.
// grid = (6, 12, 4), 256 threads.
// ---------------------------------------------------------------------------
#define SA2 36
#define SB2 264

__global__ __launch_bounds__(256, 2)
void lstm_step_mma(const float* __restrict__ Wh_hf, const float* __restrict__ Wh_hb,
                   const float* __restrict__ Wh_vf, const float* __restrict__ Wh_vb,
                   float* __restrict__ out, int s, int parity) {
    __shared__ uint32_t hs[64 * SA2];
    __shared__ uint32_t ws[32 * SB2];

    const int dir = blockIdx.z;
    const float* Wh = (dir == 0) ? Wh_hf : (dir == 1) ? Wh_hb : (dir == 2) ? Wh_vf : Wh_vb;
    const bool forward = (dir == 0) || (dir == 2);
    const int t = forward ? s : (Tc - 1 - s);

    const int c0 = blockIdx.x * 64;
    const int n0 = blockIdx.y * 64;

    const float* hprev = g_h[parity][dir];
    float*       hnext = g_h[parity ^ 1][dir];
    float*       cst   = g_c[dir];
    const float* Z     = g_z + (size_t)dir * MTOT * G4c;

    const int tid  = threadIdx.x;
    const int lane = tid & 31;
    const int wid  = tid >> 5;
    const int wm   = wid & 1;      // 0..1 (32-seq slice)
    const int wn   = wid >> 1;     // 0..3 (16-col slice)

    float acc[2][4][2][4];         // [m-tile][gate][n-tile][frag]
#pragma unroll
    for (int mt = 0; mt < 2; mt++)
#pragma unroll
        for (int g = 0; g < 4; g++)
#pragma unroll
            for (int nt = 0; nt < 2; nt++)
#pragma unroll
                for (int e = 0; e < 4; e++) acc[mt][g][nt][e] = 0.f;

    const int a_r = wm * 32 + (lane >> 2);
    const int a_c = lane & 3;
    const int b_cb = wn * 16 + (lane >> 2);
    const int b_r  = lane & 3;

    for (int kt = 0; kt < HIDc; kt += 32) {
        // Load h tile: 64 rows x 32 k, layout [m][k] stride 36, cvt tf32
#pragma unroll
        for (int q = 0; q < 2; q++) {
            int idx = tid + q * 256;
            int row = idx >> 3;
            int k4  = (idx & 7) * 4;
            float4 v = *(const float4*)&hprev[(size_t)(n0 + row) * HIDc + kt + k4];
            uint4 u = make_uint4(f2tf32(v.x), f2tf32(v.y), f2tf32(v.z), f2tf32(v.w));
            *(uint4*)&hs[row * SA2 + k4] = u;
        }
        // Load Wh tile: 32 k x (4 gates x 64 cols), layout [k][g*64+j] stride 264
#pragma unroll
        for (int q = 0; q < 8; q++) {
            int idx = tid + q * 256;
            int kk  = idx >> 6;
            int rem = idx & 63;
            int g   = rem >> 4;
            int j4  = (rem & 15) * 4;
            float4 v = *(const float4*)&Wh[(size_t)(kt + kk) * G4c + g * HIDc + c0 + j4];
            uint4 u = make_uint4(f2tf32(v.x), f2tf32(v.y), f2tf32(v.z), f2tf32(v.w));
            *(uint4*)&ws[kk * SB2 + rem * 4] = u;
        }
        __syncthreads();

#pragma unroll
        for (int k8 = 0; k8 < 4; k8++) {
            uint32_t a[2][4];
#pragma unroll
            for (int mt = 0; mt < 2; mt++) {
                int r = a_r + mt * 16;
                int c = k8 * 8 + a_c;
                a[mt][0] = hs[r * SA2 + c];
                a[mt][1] = hs[(r + 8) * SA2 + c];
                a[mt][2] = hs[r * SA2 + c + 4];
                a[mt][3] = hs[(r + 8) * SA2 + c + 4];
            }
#pragma unroll
            for (int g = 0; g < 4; g++) {
#pragma unroll
                for (int nt = 0; nt < 2; nt++) {
                    int bc = g * 64 + b_cb + nt * 8;
                    int br = k8 * 8 + b_r;
                    uint32_t b0 = ws[br * SB2 + bc];
                    uint32_t b1 = ws[(br + 4) * SB2 + bc];
                    mma_tf32(acc[0][g][nt], a[0], b0, b1);
                    mma_tf32(acc[1][g][nt], a[1], b0, b1);
                }
            }
        }
        __syncthreads();
    }

    // Epilogue: gates, state update, output write
#pragma unroll
    for (int mt = 0; mt < 2; mt++) {
#pragma unroll
        for (int nt = 0; nt < 2; nt++) {
#pragma unroll
            for (int e = 0; e < 4; e++) {
                int n = n0 + wm * 32 + mt * 16 + (lane >> 2) + ((e >= 2) ? 8 : 0);
                int j = c0 + wn * 16 + nt * 8 + 2 * (lane & 3) + (e & 1);

                size_t zb = ((size_t)n * Tc + t) * G4c + j;
                float gi = acc[mt][0][nt][e] + Z[zb];
                float gf = acc[mt][1][nt][e] + Z[zb + HIDc];
                float gg = acc[mt][2][nt][e] + Z[zb + 2 * HIDc];
                float go = acc[mt][3][nt][e] + Z[zb + 3 * HIDc];

                float iv = sigf(gi);
                float fv = sigf(gf);
                float cv = tanhf(gg);
                float ov = sigf(go);

                size_t sidx = (size_t)n * HIDc + j;
                float cn = fv * cst[sidx] + iv * cv;
                cst[sidx] = cn;
                float hn = ov * tanhf(cn);
                hnext[sidx] = hn;

                size_t orow;
                if (dir < 2) {
                    orow = (size_t)n * WGc + t;
                } else {
                    int b  = n / WGc;
                    int wg = n % WGc;
                    orow = (size_t)b * (HGc * WGc) + (size_t)t * WGc + wg;
                }
                out[orow * 1536 + (size_t)dir * HIDc + j] = hn;
            }
        }
    }
}

// ---------------------------------------------------------------------------
// Launch
// ---------------------------------------------------------------------------
extern "C" void kernel_launch(void* const* d_in, const int* in_sizes, int n_in,
                              void* d_out, int out_size) {
    const float* features = (const float*)d_in[0];
    const float* hf_Wx = (const float*)d_in[1];
    const float* hf_Wh = (const float*)d_in[2];
    const float* hf_b  = (const float*)d_in[3];
    const float* hb_Wx = (const float*)d_in[4];
    const float* hb_Wh = (const float*)d_in[5];
    const float* hb_b  = (const float*)d_in[6];
    const float* vf_Wx = (const float*)d_in[7];
    const float* vf_Wh = (const float*)d_in[8];
    const float* vf_b  = (const float*)d_in[9];
    const float* vb_Wx = (const float*)d_in[10];
    const float* vb_Wh = (const float*)d_in[11];
    const float* vb_b  = (const float*)d_in[12];
    float* out = (float*)d_out;

    // zero states
    {
        size_t n = (size_t)4 * NSEQ * HIDc;
        init_state_kernel<<<(int)((n + 255) / 256), 256>>>();
    }

    // Phase 1: input projections (mma.sync tf32), both orientations in one grid
    {
        dim3 grid(3072 / 128, MTOT / 128, 2);
        gemm_z_mma<<<grid, 256>>>(features,
                                  hf_Wx, hb_Wx, vf_Wx, vb_Wx,
                                  hf_b, hb_b, vf_b, vb_b);
    }

    // Phase 2: 24 sequential recurrence steps
    {
        dim3 grid(HIDc / 64, NSEQ / 64, 4);
        for (int s = 0; s < Tc; s++) {
            lstm_step_mma<<<grid, 256>>>(hf_Wh, hb_Wh, vf_Wh, vb_Wh, out, s, s & 1);
        }
    }
}

// round 5
// speedup vs baseline: 3.1232x; 1.0031x over previous
#include <cuda_runtime.h>
#include <math.h>
#include <stdint.h>

// Problem constants
#define NB   32
#define HGc  24
#define WGc  24
#define Dc   768
#define HIDc 384
#define G4c  1536          // 4*HID
#define Tc   24
#define NSEQ 768           // NB*24  (per direction)
#define MTOT 18432         // NSEQ*T

// Scratch (device globals — allowed; no cudaMalloc)
static __device__ float g_z[(size_t)4 * MTOT * G4c];     // z = x@Wx + b  [dir][n*T+t][1536]
static __device__ float g_h[2][4][NSEQ * HIDc];          // double-buffered hidden state
static __device__ float g_c[4][NSEQ * HIDc];             // cell state

// ---------------------------------------------------------------------------
// Helpers: tf32 convert + warp mma (base sm_103 features, no tcgen05)
// ---------------------------------------------------------------------------
__device__ __forceinline__ uint32_t f2tf32(float f) {
    uint32_t r;
    asm("cvt.rna.tf32.f32 %0, %1;" : "=r"(r) : "f"(f));
    return r;
}

__device__ __forceinline__ void mma_tf32(float (&c)[4],
                                         const uint32_t (&a)[4],
                                         uint32_t b0, uint32_t b1) {
    asm volatile(
        "mma.sync.aligned.m16n8k8.row.col.f32.tf32.tf32.f32 "
        "{%0,%1,%2,%3}, {%4,%5,%6,%7}, {%8,%9}, {%0,%1,%2,%3};"
        : "+f"(c[0]), "+f"(c[1]), "+f"(c[2]), "+f"(c[3])
        : "r"(a[0]), "r"(a[1]), "r"(a[2]), "r"(a[3]), "r"(b0), "r"(b1));
}

__device__ __forceinline__ float sigf(float x) {
    return 1.f / (1.f + __expf(-x));
}

// ---------------------------------------------------------------------------
// Zero-init h (both parities) and c
// ---------------------------------------------------------------------------
__global__ void init_state_kernel() {
    size_t i = (size_t)blockIdx.x * blockDim.x + threadIdx.x;
    const size_t n = (size_t)4 * NSEQ * HIDc;
    if (i < n) {
        ((float*)g_h)[i]     = 0.f;
        ((float*)g_h)[n + i] = 0.f;
        ((float*)g_c)[i]     = 0.f;
    }
}

// ---------------------------------------------------------------------------
// Phase 1: z = x @ Wx + b via mma.sync tf32.
// CTA tile 128(M) x 128(N), K=768 chunked by 32.
// 8 warps = 4(M) x 2(N); warp tile 32x64 -> 2 m16-tiles x 8 n8-tiles.
// SMEM: A[m][k] stride 36 (conflict-free frags), B[k][n] stride 136.
// grid = (24 col tiles of 3072, 144 row tiles, 2 orientations)
// ---------------------------------------------------------------------------
#define SA1 36
#define SB1 136

__global__ __launch_bounds__(256, 2)
void gemm_z_mma(const float* __restrict__ feat,
                const float* __restrict__ Whf, const float* __restrict__ Whb,
                const float* __restrict__ Wvf, const float* __restrict__ Wvb,
                const float* __restrict__ bhf, const float* __restrict__ bhb,
                const float* __restrict__ bvf, const float* __restrict__ bvb) {
    __shared__ uint32_t As[128 * SA1];
    __shared__ uint32_t Bs[32 * SB1];

    const int tid  = threadIdx.x;
    const int lane = tid & 31;
    const int wid  = tid >> 5;
    const int wm   = wid & 3;      // 0..3
    const int wn   = wid >> 2;     // 0..1

    const int bx = blockIdx.x;           // 0..23 (cols of 3072)
    const int by = blockIdx.y;           // 0..143
    const int orient = blockIdx.z;       // 0=H, 1=V

    const int gc0  = bx * 128;
    const int half = (gc0 >= G4c) ? 1 : 0;
    const int wc0  = gc0 - half * G4c;
    const int dir  = orient * 2 + half;
    const float* W    = (orient == 0) ? (half ? Whb : Whf) : (half ? Wvb : Wvf);
    const float* bias = (orient == 0) ? (half ? bhb : bhf) : (half ? bvb : bvf);
    const int m0 = by * 128;

    // Per-thread A row pointers (row gather for vertical orientation)
    const float* aptr[4];
#pragma unroll
    for (int q = 0; q < 4; q++) {
        int row = (tid >> 3) + q * 32;
        int m = m0 + row;
        int rf;
        if (orient == 0) {
            rf = m;
        } else {
            int t  = m % 24;
            int nn = m / 24;
            int wg = nn % 24;
            int b  = nn / 24;
            rf = b * 576 + t * 24 + wg;
        }
        aptr[q] = feat + (size_t)rf * Dc + (tid & 7) * 4;
    }

    float acc[2][8][4];
#pragma unroll
    for (int mt = 0; mt < 2; mt++)
#pragma unroll
        for (int nt = 0; nt < 8; nt++)
#pragma unroll
            for (int e = 0; e < 4; e++) acc[mt][nt][e] = 0.f;

    const int a_r = wm * 32 + (lane >> 2);
    const int a_c = lane & 3;
    const int b_c = wn * 64 + (lane >> 2);
    const int b_r = lane & 3;

    for (int kt = 0; kt < Dc; kt += 32) {
        // Load A tile: 128 rows x 32 k (cvt to tf32)
#pragma unroll
        for (int q = 0; q < 4; q++) {
            float4 v = *(const float4*)(aptr[q] + kt);
            uint4 u = make_uint4(f2tf32(v.x), f2tf32(v.y), f2tf32(v.z), f2tf32(v.w));
            int row = (tid >> 3) + q * 32;
            *(uint4*)&As[row * SA1 + (tid & 7) * 4] = u;
        }
        // Load B tile: 32 k x 128 n
#pragma unroll
        for (int q = 0; q < 4; q++) {
            int kk = (tid >> 5) + q * 8;
            float4 v = *(const float4*)(W + (size_t)(kt + kk) * G4c + wc0 + (tid & 31) * 4);
            uint4 u = make_uint4(f2tf32(v.x), f2tf32(v.y), f2tf32(v.z), f2tf32(v.w));
            *(uint4*)&Bs[kk * SB1 + (tid & 31) * 4] = u;
        }
        __syncthreads();

#pragma unroll
        for (int k8 = 0; k8 < 4; k8++) {
            uint32_t a[2][4];
#pragma unroll
            for (int mt = 0; mt < 2; mt++) {
                int r = a_r + mt * 16;
                int c = k8 * 8 + a_c;
                a[mt][0] = As[r * SA1 + c];
                a[mt][1] = As[(r + 8) * SA1 + c];
                a[mt][2] = As[r * SA1 + c + 4];
                a[mt][3] = As[(r + 8) * SA1 + c + 4];
            }
#pragma unroll
            for (int nt = 0; nt < 8; nt++) {
                int bc = b_c + nt * 8;
                int br = k8 * 8 + b_r;
                uint32_t b0 = Bs[br * SB1 + bc];
                uint32_t b1 = Bs[(br + 4) * SB1 + bc];
                mma_tf32(acc[0][nt], a[0], b0, b1);
                mma_tf32(acc[1][nt], a[1], b0, b1);
            }
        }
        __syncthreads();
    }

    // Epilogue: add bias, store directly
    float* Zt = g_z + (size_t)dir * MTOT * G4c;
#pragma unroll
    for (int mt = 0; mt < 2; mt++) {
        int r = m0 + wm * 32 + mt * 16 + (lane >> 2);
#pragma unroll
        for (int nt = 0; nt < 8; nt++) {
            int c = wc0 + wn * 64 + nt * 8 + 2 * (lane & 3);
            float bv0 = __ldg(&bias[c]);
            float bv1 = __ldg(&bias[c + 1]);
            float2 v0 = make_float2(acc[mt][nt][0] + bv0, acc[mt][nt][1] + bv1);
            float2 v1 = make_float2(acc[mt][nt][2] + bv0, acc[mt][nt][3] + bv1);
            *(float2*)&Zt[(size_t)r * G4c + c]       = v0;
            *(float2*)&Zt[(size_t)(r + 8) * G4c + c] = v1;
        }
    }
}

// ---------------------------------------------------------------------------
// Phase 2: one LSTM step, all 4 directions, mma.sync tf32.
// CTA: 64 seqs x 64 hidden cols (x4 gates = 256 N cols), K=384 chunked by 32.
// 8 warps = 2(M) x 4(N); warp tile 32 seqs x 16 cols -> per k8:
// 2 m16-tiles x (4 gates x 2 n8-tiles) = 16 mma.
// grid = (6, 12, 4), 256 threads.
// ---------------------------------------------------------------------------
#define SA2 36
#define SB2 264

__global__ __launch_bounds__(256, 2)
void lstm_step_mma(const float* __restrict__ Wh_hf, const float* __restrict__ Wh_hb,
                   const float* __restrict__ Wh_vf, const float* __restrict__ Wh_vb,
                   float* __restrict__ out, int s, int parity) {
    __shared__ uint32_t hs[64 * SA2];
    __shared__ uint32_t ws[32 * SB2];

    const int dir = blockIdx.z;
    const float* Wh = (dir == 0) ? Wh_hf : (dir == 1) ? Wh_hb : (dir == 2) ? Wh_vf : Wh_vb;
    const bool forward = (dir == 0) || (dir == 2);
    const int t = forward ? s : (Tc - 1 - s);

    const int c0 = blockIdx.x * 64;
    const int n0 = blockIdx.y * 64;

    const float* hprev = g_h[parity][dir];
    float*       hnext = g_h[parity ^ 1][dir];
    float*       cst   = g_c[dir];
    const float* Z     = g_z + (size_t)dir * MTOT * G4c;

    const int tid  = threadIdx.x;
    const int lane = tid & 31;
    const int wid  = tid >> 5;
    const int wm   = wid & 1;      // 0..1 (32-seq slice)
    const int wn   = wid >> 1;     // 0..3 (16-col slice)

    float acc[2][4][2][4];         // [m-tile][gate][n-tile][frag]
#pragma unroll
    for (int mt = 0; mt < 2; mt++)
#pragma unroll
        for (int g = 0; g < 4; g++)
#pragma unroll
            for (int nt = 0; nt < 2; nt++)
#pragma unroll
                for (int e = 0; e < 4; e++) acc[mt][g][nt][e] = 0.f;

    const int a_r = wm * 32 + (lane >> 2);
    const int a_c = lane & 3;
    const int b_cb = wn * 16 + (lane >> 2);
    const int b_r  = lane & 3;

    for (int kt = 0; kt < HIDc; kt += 32) {
        // Load h tile: 64 rows x 32 k, layout [m][k] stride 36, cvt tf32
#pragma unroll
        for (int q = 0; q < 2; q++) {
            int idx = tid + q * 256;
            int row = idx >> 3;
            int k4  = (idx & 7) * 4;
            float4 v = *(const float4*)&hprev[(size_t)(n0 + row) * HIDc + kt + k4];
            uint4 u = make_uint4(f2tf32(v.x), f2tf32(v.y), f2tf32(v.z), f2tf32(v.w));
            *(uint4*)&hs[row * SA2 + k4] = u;
        }
        // Load Wh tile: 32 k x (4 gates x 64 cols), layout [k][g*64+j] stride 264
#pragma unroll
        for (int q = 0; q < 8; q++) {
            int idx = tid + q * 256;
            int kk  = idx >> 6;
            int rem = idx & 63;
            int g   = rem >> 4;
            int j4  = (rem & 15) * 4;
            float4 v = *(const float4*)&Wh[(size_t)(kt + kk) * G4c + g * HIDc + c0 + j4];
            uint4 u = make_uint4(f2tf32(v.x), f2tf32(v.y), f2tf32(v.z), f2tf32(v.w));
            *(uint4*)&ws[kk * SB2 + rem * 4] = u;
        }
        __syncthreads();

#pragma unroll
        for (int k8 = 0; k8 < 4; k8++) {
            uint32_t a[2][4];
#pragma unroll
            for (int mt = 0; mt < 2; mt++) {
                int r = a_r + mt * 16;
                int c = k8 * 8 + a_c;
                a[mt][0] = hs[r * SA2 + c];
                a[mt][1] = hs[(r + 8) * SA2 + c];
                a[mt][2] = hs[r * SA2 + c + 4];
                a[mt][3] = hs[(r + 8) * SA2 + c + 4];
            }
#pragma unroll
            for (int g = 0; g < 4; g++) {
#pragma unroll
                for (int nt = 0; nt < 2; nt++) {
                    int bc = g * 64 + b_cb + nt * 8;
                    int br = k8 * 8 + b_r;
                    uint32_t b0 = ws[br * SB2 + bc];
                    uint32_t b1 = ws[(br + 4) * SB2 + bc];
                    mma_tf32(acc[0][g][nt], a[0], b0, b1);
                    mma_tf32(acc[1][g][nt], a[1], b0, b1);
                }
            }
        }
        __syncthreads();
    }

    // Epilogue: gates, state update, output write
#pragma unroll
    for (int mt = 0; mt < 2; mt++) {
#pragma unroll
        for (int nt = 0; nt < 2; nt++) {
#pragma unroll
            for (int e = 0; e < 4; e++) {
                int n = n0 + wm * 32 + mt * 16 + (lane >> 2) + ((e >= 2) ? 8 : 0);
                int j = c0 + wn * 16 + nt * 8 + 2 * (lane & 3) + (e & 1);

                size_t zb = ((size_t)n * Tc + t) * G4c + j;
                float gi = acc[mt][0][nt][e] + Z[zb];
                float gf = acc[mt][1][nt][e] + Z[zb + HIDc];
                float gg = acc[mt][2][nt][e] + Z[zb + 2 * HIDc];
                float go = acc[mt][3][nt][e] + Z[zb + 3 * HIDc];

                float iv = sigf(gi);
                float fv = sigf(gf);
                float cv = tanhf(gg);
                float ov = sigf(go);

                size_t sidx = (size_t)n * HIDc + j;
                float cn = fv * cst[sidx] + iv * cv;
                cst[sidx] = cn;
                float hn = ov * tanhf(cn);
                hnext[sidx] = hn;

                size_t orow;
                if (dir < 2) {
                    orow = (size_t)n * WGc + t;
                } else {
                    int b  = n / WGc;
                    int wg = n % WGc;
                    orow = (size_t)b * (HGc * WGc) + (size_t)t * WGc + wg;
                }
                out[orow * 1536 + (size_t)dir * HIDc + j] = hn;
            }
        }
    }
}

// ---------------------------------------------------------------------------
// Launch
// ---------------------------------------------------------------------------
extern "C" void kernel_launch(void* const* d_in, const int* in_sizes, int n_in,
                              void* d_out, int out_size) {
    const float* features = (const float*)d_in[0];
    const float* hf_Wx = (const float*)d_in[1];
    const float* hf_Wh = (const float*)d_in[2];
    const float* hf_b  = (const float*)d_in[3];
    const float* hb_Wx = (const float*)d_in[4];
    const float* hb_Wh = (const float*)d_in[5];
    const float* hb_b  = (const float*)d_in[6];
    const float* vf_Wx = (const float*)d_in[7];
    const float* vf_Wh = (const float*)d_in[8];
    const float* vf_b  = (const float*)d_in[9];
    const float* vb_Wx = (const float*)d_in[10];
    const float* vb_Wh = (const float*)d_in[11];
    const float* vb_b  = (const float*)d_in[12];
    float* out = (float*)d_out;

    // zero states
    {
        size_t n = (size_t)4 * NSEQ * HIDc;
        init_state_kernel<<<(int)((n + 255) / 256), 256>>>();
    }

    // Phase 1: input projections (mma.sync tf32), both orientations in one grid
    {
        dim3 grid(3072 / 128, MTOT / 128, 2);
        gemm_z_mma<<<grid, 256>>>(features,
                                  hf_Wx, hb_Wx, vf_Wx, vb_Wx,
                                  hf_b, hb_b, vf_b, vb_b);
    }

    // Phase 2: 24 sequential recurrence steps
    {
        dim3 grid(HIDc / 64, NSEQ / 64, 4);
        for (int s = 0; s < Tc; s++) {
            lstm_step_mma<<<grid, 256>>>(hf_Wh, hb_Wh, vf_Wh, vb_Wh, out, s, s & 1);
        }
    }
}

// round 6
// speedup vs baseline: 3.6160x; 1.1578x over previous
#include <cuda_runtime.h>
#include <math.h>
#include <stdint.h>

// Problem constants
#define NB   32
#define HGc  24
#define WGc  24
#define Dc   768
#define HIDc 384
#define G4c  1536          // 4*HID
#define Tc   24
#define NSEQ 768           // NB*24  (per direction)
#define MTOT 18432         // NSEQ*T

// Scratch (device globals — allowed; no cudaMalloc)
static __device__ float    g_z[(size_t)4 * MTOT * G4c];     // z = x@Wx + b
static __device__ uint32_t g_h[2][4][NSEQ * HIDc];          // hidden state (tf32 words)
static __device__ float    g_c[4][NSEQ * HIDc];             // cell state
static __device__ uint32_t g_x[(size_t)2 * MTOT * Dc];      // features tf32, [orient][m][768] (V pre-gathered)
static __device__ uint32_t g_wx[(size_t)4 * Dc * G4c];      // Wx tf32
static __device__ uint32_t g_wh[(size_t)4 * HIDc * G4c];    // Wh tf32

// ---------------------------------------------------------------------------
// Helpers
// ---------------------------------------------------------------------------
__device__ __forceinline__ uint32_t smem_u32(const void* p) {
    uint32_t a;
    asm("{ .reg .u64 t; cvta.to.shared.u64 t, %1; cvt.u32.u64 %0, t; }" : "=r"(a) : "l"(p));
    return a;
}
__device__ __forceinline__ uint32_t f2tf32(float f) {
    uint32_t r;
    asm("cvt.rna.tf32.f32 %0, %1;" : "=r"(r) : "f"(f));
    return r;
}
__device__ __forceinline__ void cp16(uint32_t dst, const void* src) {
    asm volatile("cp.async.cg.shared.global [%0], [%1], 16;" :: "r"(dst), "l"(src));
}
#define CP_COMMIT() asm volatile("cp.async.commit_group;" ::: "memory")
#define CP_WAIT1()  asm volatile("cp.async.wait_group 1;" ::: "memory")
#define CP_WAIT0()  asm volatile("cp.async.wait_group 0;" ::: "memory")

__device__ __forceinline__ void mma_tf32(float (&c)[4],
                                         const uint32_t (&a)[4],
                                         uint32_t b0, uint32_t b1) {
    asm volatile(
        "mma.sync.aligned.m16n8k8.row.col.f32.tf32.tf32.f32 "
        "{%0,%1,%2,%3}, {%4,%5,%6,%7}, {%8,%9}, {%0,%1,%2,%3};"
        : "+f"(c[0]), "+f"(c[1]), "+f"(c[2]), "+f"(c[3])
        : "r"(a[0]), "r"(a[1]), "r"(a[2]), "r"(a[3]), "r"(b0), "r"(b1));
}

__device__ __forceinline__ float sigf(float x) {
    return 1.f / (1.f + __expf(-x));
}

// ---------------------------------------------------------------------------
// Init: zero h (tf32(0)=0) and c
// ---------------------------------------------------------------------------
__global__ void init_state_kernel() {
    size_t i = (size_t)blockIdx.x * blockDim.x + threadIdx.x;
    const size_t n = (size_t)4 * NSEQ * HIDc;
    if (i < n) {
        ((uint32_t*)g_h)[i]     = 0u;
        ((uint32_t*)g_h)[n + i] = 0u;
        ((float*)g_c)[i]        = 0.f;
    }
}

// ---------------------------------------------------------------------------
// Pre-pass: convert features to tf32 (orient 0 straight, orient 1 gathered)
// one float4 per thread; total 2*18432*192 float4
// ---------------------------------------------------------------------------
__global__ void convert_x_kernel(const float* __restrict__ feat) {
    size_t i = (size_t)blockIdx.x * blockDim.x + threadIdx.x;
    const size_t half = (size_t)MTOT * (Dc / 4);
    if (i >= 2 * half) return;
    int orient = (i >= half) ? 1 : 0;
    size_t r = i - (orient ? half : 0);
    int m  = (int)(r / (Dc / 4));
    int k4 = (int)(r % (Dc / 4)) * 4;
    int rf;
    if (!orient) {
        rf = m;
    } else {
        int t  = m % 24;
        int nn = m / 24;
        int wg = nn % 24;
        int b  = nn / 24;
        rf = b * 576 + t * 24 + wg;
    }
    float4 v = *(const float4*)(feat + (size_t)rf * Dc + k4);
    uint4 u = make_uint4(f2tf32(v.x), f2tf32(v.y), f2tf32(v.z), f2tf32(v.w));
    *(uint4*)(g_x + (size_t)orient * MTOT * Dc + (size_t)m * Dc + k4) = u;
}

// ---------------------------------------------------------------------------
// Pre-pass: convert all 8 weight matrices to tf32 (same layout)
// ---------------------------------------------------------------------------
__global__ void convert_w_kernel(const float* __restrict__ whfx, const float* __restrict__ whbx,
                                 const float* __restrict__ wvfx, const float* __restrict__ wvbx,
                                 const float* __restrict__ whfh, const float* __restrict__ whbh,
                                 const float* __restrict__ wvfh, const float* __restrict__ wvbh) {
    size_t i = (size_t)blockIdx.x * blockDim.x + threadIdx.x;
    const size_t nx = (size_t)Dc * G4c / 4;      // 294912 per wx
    const size_t nh = (size_t)HIDc * G4c / 4;    // 147456 per wh
    const float* src;
    uint32_t* dst;
    size_t r;
    if (i < 4 * nx) {
        int dir = (int)(i / nx);
        r = i % nx;
        src = (dir == 0) ? whfx : (dir == 1) ? whbx : (dir == 2) ? wvfx : wvbx;
        dst = g_wx + (size_t)dir * Dc * G4c;
    } else if (i < 4 * nx + 4 * nh) {
        size_t j = i - 4 * nx;
        int dir = (int)(j / nh);
        r = j % nh;
        src = (dir == 0) ? whfh : (dir == 1) ? whbh : (dir == 2) ? wvfh : wvbh;
        dst = g_wh + (size_t)dir * HIDc * G4c;
    } else {
        return;
    }
    float4 v = *(const float4*)(src + r * 4);
    uint4 u = make_uint4(f2tf32(v.x), f2tf32(v.y), f2tf32(v.z), f2tf32(v.w));
    *(uint4*)(dst + r * 4) = u;
}

// ---------------------------------------------------------------------------
// Phase 1: z = x @ Wx + b via mma.sync tf32, cp.async 2-stage pipeline.
// CTA 128x128, K=768 in 24 chunks of 32. 8 warps = 4(M) x 2(N).
// SMEM (elems): As[2][128*36]=9216, Bs[2][32*136]=8704 -> 71680 bytes.
// ---------------------------------------------------------------------------
#define SA1 36
#define SB1 136
#define A1SZ (128 * SA1)
#define B1SZ (32 * SB1)

__global__ __launch_bounds__(256, 2)
void gemm_z_mma(const float* __restrict__ bhf, const float* __restrict__ bhb,
                const float* __restrict__ bvf, const float* __restrict__ bvb) {
    extern __shared__ uint32_t sm1[];
    const uint32_t sbase = smem_u32(sm1);

    const int tid  = threadIdx.x;
    const int lane = tid & 31;
    const int wid  = tid >> 5;
    const int wm   = wid & 3;
    const int wn   = wid >> 2;

    const int bx = blockIdx.x;
    const int by = blockIdx.y;
    const int orient = blockIdx.z;

    const int gc0  = bx * 128;
    const int half = (gc0 >= G4c) ? 1 : 0;
    const int wc0  = gc0 - half * G4c;
    const int dir  = orient * 2 + half;
    const float* bias = (orient == 0) ? (half ? bhb : bhf) : (half ? bvb : bvf);
    const int m0 = by * 128;

    // source pointers
    const uint32_t* asrc[4];
#pragma unroll
    for (int q = 0; q < 4; q++) {
        int row = (tid >> 3) + q * 32;
        asrc[q] = g_x + (size_t)orient * MTOT * Dc + (size_t)(m0 + row) * Dc + (tid & 7) * 4;
    }
    const uint32_t* bsrc = g_wx + (size_t)dir * Dc * G4c + wc0 + (tid & 31) * 4;

    // smem dst addresses (byte)
    const uint32_t adst = sbase + (((tid >> 3)) * SA1 + (tid & 7) * 4) * 4;
    const uint32_t bdst = sbase + (2 * A1SZ + ((tid >> 5)) * SB1 + (tid & 31) * 4) * 4;

    float acc[2][8][4];
#pragma unroll
    for (int mt = 0; mt < 2; mt++)
#pragma unroll
        for (int nt = 0; nt < 8; nt++)
#pragma unroll
            for (int e = 0; e < 4; e++) acc[mt][nt][e] = 0.f;

    const int a_r = wm * 32 + (lane >> 2);
    const int a_c = lane & 3;
    const int b_c = wn * 64 + (lane >> 2);
    const int b_r = lane & 3;

#define LOAD1(c, buf) do {                                                      \
    int kt_ = (c) * 32;                                                         \
    uint32_t ao = adst + (buf) * (A1SZ * 4);                                    \
    uint32_t bo = bdst + (buf) * (B1SZ * 4);                                    \
    _Pragma("unroll")                                                           \
    for (int q = 0; q < 4; q++)                                                 \
        cp16(ao + q * 32 * SA1 * 4, asrc[q] + kt_);                             \
    _Pragma("unroll")                                                           \
    for (int q = 0; q < 4; q++)                                                 \
        cp16(bo + q * 8 * SB1 * 4, bsrc + (size_t)(kt_ + (tid >> 5) + q * 8) * G4c); \
    CP_COMMIT();                                                                \
} while (0)

    LOAD1(0, 0);
    for (int c = 0; c < 24; c++) {
        const int buf = c & 1;
        if (c + 1 < 24) { LOAD1(c + 1, buf ^ 1); CP_WAIT1(); }
        else            { CP_WAIT0(); }
        __syncthreads();

        const uint32_t* A = sm1 + buf * A1SZ;
        const uint32_t* B = sm1 + 2 * A1SZ + buf * B1SZ;
#pragma unroll
        for (int k8 = 0; k8 < 4; k8++) {
            uint32_t a[2][4];
#pragma unroll
            for (int mt = 0; mt < 2; mt++) {
                int r = a_r + mt * 16;
                int cc = k8 * 8 + a_c;
                a[mt][0] = A[r * SA1 + cc];
                a[mt][1] = A[(r + 8) * SA1 + cc];
                a[mt][2] = A[r * SA1 + cc + 4];
                a[mt][3] = A[(r + 8) * SA1 + cc + 4];
            }
#pragma unroll
            for (int nt = 0; nt < 8; nt++) {
                int bc = b_c + nt * 8;
                int br = k8 * 8 + b_r;
                uint32_t b0 = B[br * SB1 + bc];
                uint32_t b1 = B[(br + 4) * SB1 + bc];
                mma_tf32(acc[0][nt], a[0], b0, b1);
                mma_tf32(acc[1][nt], a[1], b0, b1);
            }
        }
        __syncthreads();
    }
#undef LOAD1

    // Epilogue
    float* Zt = g_z + (size_t)dir * MTOT * G4c;
#pragma unroll
    for (int mt = 0; mt < 2; mt++) {
        int r = m0 + wm * 32 + mt * 16 + (lane >> 2);
#pragma unroll
        for (int nt = 0; nt < 8; nt++) {
            int c = wc0 + wn * 64 + nt * 8 + 2 * (lane & 3);
            float bv0 = __ldg(&bias[c]);
            float bv1 = __ldg(&bias[c + 1]);
            float2 v0 = make_float2(acc[mt][nt][0] + bv0, acc[mt][nt][1] + bv1);
            float2 v1 = make_float2(acc[mt][nt][2] + bv0, acc[mt][nt][3] + bv1);
            *(float2*)&Zt[(size_t)r * G4c + c]       = v0;
            *(float2*)&Zt[(size_t)(r + 8) * G4c + c] = v1;
        }
    }
}

// ---------------------------------------------------------------------------
// Phase 2: one LSTM step, cp.async 2-stage pipeline, tf32 mma.
// CTA: 64 seqs x 64 cols x 4 gates, K=384 in 12 chunks of 32.
// SMEM (elems): hs[2][64*36]=4608, ws[2][32*264]=16896 -> 86016 bytes.
// ---------------------------------------------------------------------------
#define SA2 36
#define SB2 264
#define A2SZ (64 * SA2)
#define B2SZ (32 * SB2)

__global__ __launch_bounds__(256, 2)
void lstm_step_mma(float* __restrict__ out, int s, int parity) {
    extern __shared__ uint32_t sm2[];
    const uint32_t sbase = smem_u32(sm2);

    const int dir = blockIdx.z;
    const bool forward = (dir == 0) || (dir == 2);
    const int t = forward ? s : (Tc - 1 - s);

    const int c0 = blockIdx.x * 64;
    const int n0 = blockIdx.y * 64;

    const uint32_t* hprev = g_h[parity][dir];
    uint32_t*       hnext = g_h[parity ^ 1][dir];
    float*          cst   = g_c[dir];
    const float*    Z     = g_z + (size_t)dir * MTOT * G4c;
    const uint32_t* Wh    = g_wh + (size_t)dir * HIDc * G4c;

    const int tid  = threadIdx.x;
    const int lane = tid & 31;
    const int wid  = tid >> 5;
    const int wm   = wid & 1;
    const int wn   = wid >> 1;

    float acc[2][4][2][4];
#pragma unroll
    for (int mt = 0; mt < 2; mt++)
#pragma unroll
        for (int g = 0; g < 4; g++)
#pragma unroll
            for (int nt = 0; nt < 2; nt++)
#pragma unroll
                for (int e = 0; e < 4; e++) acc[mt][g][nt][e] = 0.f;

    const int a_r  = wm * 32 + (lane >> 2);
    const int a_c  = lane & 3;
    const int b_cb = wn * 16 + (lane >> 2);
    const int b_r  = lane & 3;

    // per-thread load geometry
    const int arow0 = tid >> 3;            // +32 for q=1
    const int ak4   = (tid & 7) * 4;
    const uint32_t* hsrc = hprev + (size_t)(n0 + arow0) * HIDc + ak4;

#define LOAD2(c, buf) do {                                                        \
    int kt_ = (c) * 32;                                                           \
    _Pragma("unroll")                                                             \
    for (int q = 0; q < 2; q++) {                                                 \
        uint32_t dst = sbase + ((buf) * A2SZ + (arow0 + q * 32) * SA2 + ak4) * 4; \
        cp16(dst, hsrc + (size_t)q * 32 * HIDc + kt_);                            \
    }                                                                             \
    _Pragma("unroll")                                                             \
    for (int q = 0; q < 8; q++) {                                                 \
        int idx = tid + q * 256;                                                  \
        int kk  = idx >> 6;                                                       \
        int rem = idx & 63;                                                       \
        uint32_t dst = sbase + (2 * A2SZ + (buf) * B2SZ + kk * SB2 + rem * 4) * 4;\
        cp16(dst, Wh + (size_t)(kt_ + kk) * G4c + (rem >> 4) * HIDc + c0 + (rem & 15) * 4); \
    }                                                                             \
    CP_COMMIT();                                                                  \
} while (0)

    LOAD2(0, 0);
    for (int c = 0; c < 12; c++) {
        const int buf = c & 1;
        if (c + 1 < 12) { LOAD2(c + 1, buf ^ 1); CP_WAIT1(); }
        else            { CP_WAIT0(); }
        __syncthreads();

        const uint32_t* hs = sm2 + buf * A2SZ;
        const uint32_t* ws = sm2 + 2 * A2SZ + buf * B2SZ;
#pragma unroll
        for (int k8 = 0; k8 < 4; k8++) {
            uint32_t a[2][4];
#pragma unroll
            for (int mt = 0; mt < 2; mt++) {
                int r = a_r + mt * 16;
                int cc = k8 * 8 + a_c;
                a[mt][0] = hs[r * SA2 + cc];
                a[mt][1] = hs[(r + 8) * SA2 + cc];
                a[mt][2] = hs[r * SA2 + cc + 4];
                a[mt][3] = hs[(r + 8) * SA2 + cc + 4];
            }
#pragma unroll
            for (int g = 0; g < 4; g++) {
#pragma unroll
                for (int nt = 0; nt < 2; nt++) {
                    int bc = g * 64 + b_cb + nt * 8;
                    int br = k8 * 8 + b_r;
                    uint32_t b0 = ws[br * SB2 + bc];
                    uint32_t b1 = ws[(br + 4) * SB2 + bc];
                    mma_tf32(acc[0][g][nt], a[0], b0, b1);
                    mma_tf32(acc[1][g][nt], a[1], b0, b1);
                }
            }
        }
        __syncthreads();
    }
#undef LOAD2

    // Epilogue: gates + state update + output, float2-vectorized
#pragma unroll
    for (int mt = 0; mt < 2; mt++) {
        int rbase = n0 + wm * 32 + mt * 16 + (lane >> 2);
#pragma unroll
        for (int nt = 0; nt < 2; nt++) {
            int j = c0 + wn * 16 + nt * 8 + 2 * (lane & 3);
#pragma unroll
            for (int hh = 0; hh < 2; hh++) {
                int n = rbase + 8 * hh;
                int e0 = 2 * hh;          // frag index for (j), e0+1 for (j+1)
                size_t zb = ((size_t)n * Tc + t) * G4c + j;
                float2 zi = *(const float2*)&Z[zb];
                float2 zf = *(const float2*)&Z[zb + HIDc];
                float2 zg = *(const float2*)&Z[zb + 2 * HIDc];
                float2 zo = *(const float2*)&Z[zb + 3 * HIDc];

                float gi0 = acc[mt][0][nt][e0]     + zi.x;
                float gi1 = acc[mt][0][nt][e0 + 1] + zi.y;
                float gf0 = acc[mt][1][nt][e0]     + zf.x;
                float gf1 = acc[mt][1][nt][e0 + 1] + zf.y;
                float gg0 = acc[mt][2][nt][e0]     + zg.x;
                float gg1 = acc[mt][2][nt][e0 + 1] + zg.y;
                float go0 = acc[mt][3][nt][e0]     + zo.x;
                float go1 = acc[mt][3][nt][e0 + 1] + zo.y;

                size_t sidx = (size_t)n * HIDc + j;
                float2 cold = *(const float2*)&cst[sidx];
                float cn0 = sigf(gf0) * cold.x + sigf(gi0) * tanhf(gg0);
                float cn1 = sigf(gf1) * cold.y + sigf(gi1) * tanhf(gg1);
                *(float2*)&cst[sidx] = make_float2(cn0, cn1);

                float hn0 = sigf(go0) * tanhf(cn0);
                float hn1 = sigf(go1) * tanhf(cn1);
                *(uint2*)&hnext[sidx] = make_uint2(f2tf32(hn0), f2tf32(hn1));

                size_t orow;
                if (dir < 2) {
                    orow = (size_t)n * WGc + t;
                } else {
                    int b  = n / WGc;
                    int wg = n % WGc;
                    orow = (size_t)b * (HGc * WGc) + (size_t)t * WGc + wg;
                }
                *(float2*)&out[orow * 1536 + (size_t)dir * HIDc + j] = make_float2(hn0, hn1);
            }
        }
    }
}

// ---------------------------------------------------------------------------
// Launch
// ---------------------------------------------------------------------------
extern "C" void kernel_launch(void* const* d_in, const int* in_sizes, int n_in,
                              void* d_out, int out_size) {
    const float* features = (const float*)d_in[0];
    const float* hf_Wx = (const float*)d_in[1];
    const float* hf_Wh = (const float*)d_in[2];
    const float* hf_b  = (const float*)d_in[3];
    const float* hb_Wx = (const float*)d_in[4];
    const float* hb_Wh = (const float*)d_in[5];
    const float* hb_b  = (const float*)d_in[6];
    const float* vf_Wx = (const float*)d_in[7];
    const float* vf_Wh = (const float*)d_in[8];
    const float* vf_b  = (const float*)d_in[9];
    const float* vb_Wx = (const float*)d_in[10];
    const float* vb_Wh = (const float*)d_in[11];
    const float* vb_b  = (const float*)d_in[12];
    float* out = (float*)d_out;

    const int smem1 = 2 * (A1SZ + B1SZ) * 4;   // 71680
    const int smem2 = 2 * (A2SZ + B2SZ) * 4;   // 86016
    cudaFuncSetAttribute(gemm_z_mma,    cudaFuncAttributeMaxDynamicSharedMemorySize, smem1);
    cudaFuncSetAttribute(lstm_step_mma, cudaFuncAttributeMaxDynamicSharedMemorySize, smem2);

    // init states
    {
        size_t n = (size_t)4 * NSEQ * HIDc;
        init_state_kernel<<<(int)((n + 255) / 256), 256>>>();
    }
    // pre-convert features + weights to tf32
    {
        size_t nx = (size_t)2 * MTOT * (Dc / 4);
        convert_x_kernel<<<(int)((nx + 255) / 256), 256>>>(features);
        size_t nw = (size_t)4 * Dc * G4c / 4 + (size_t)4 * HIDc * G4c / 4;
        convert_w_kernel<<<(int)((nw + 255) / 256), 256>>>(
            hf_Wx, hb_Wx, vf_Wx, vb_Wx, hf_Wh, hb_Wh, vf_Wh, vb_Wh);
    }
    // Phase 1
    {
        dim3 grid(3072 / 128, MTOT / 128, 2);
        gemm_z_mma<<<grid, 256, smem1>>>(hf_b, hb_b, vf_b, vb_b);
    }
    // Phase 2
    {
        dim3 grid(HIDc / 64, NSEQ / 64, 4);
        for (int s = 0; s < Tc; s++) {
            lstm_step_mma<<<grid, 256, smem2>>>(out, s, s & 1);
        }
    }
}

// round 7
// speedup vs baseline: 4.3442x; 1.2014x over previous
#include <cuda_runtime.h>
#include <math.h>
#include <stdint.h>

// Problem constants
#define NB   32
#define HGc  24
#define WGc  24
#define Dc   768
#define HIDc 384
#define G4c  1536
#define Tc   24
#define NSEQ 768
#define MTOT 18432

// Fragment-layout scratch (device globals)
static __device__ float    g_z[(size_t)4 * MTOT * G4c];
static __device__ uint32_t g_h[2][4][NSEQ * HIDc];        // h state, A-fragment layout, tf32
static __device__ float    g_c[4][NSEQ * HIDc];
static __device__ uint32_t g_x[(size_t)2 * MTOT * Dc];    // features, A-frag layout per 128x32 chunk
static __device__ uint32_t g_wx[(size_t)4 * Dc * G4c];    // Wx, B-frag layout per 32x128 chunk
static __device__ uint32_t g_wh[(size_t)4 * HIDc * G4c];  // Wh, B-frag layout per 32x256 chunk

// ---------------------------------------------------------------------------
// Helpers
// ---------------------------------------------------------------------------
__device__ __forceinline__ uint32_t smem_u32(const void* p) {
    uint32_t a;
    asm("{ .reg .u64 t; cvta.to.shared.u64 t, %1; cvt.u32.u64 %0, t; }" : "=r"(a) : "l"(p));
    return a;
}
__device__ __forceinline__ uint32_t f2tf32(float f) {
    uint32_t r;
    asm("cvt.rna.tf32.f32 %0, %1;" : "=r"(r) : "f"(f));
    return r;
}
__device__ __forceinline__ void cp16(uint32_t dst, const void* src) {
    asm volatile("cp.async.cg.shared.global [%0], [%1], 16;" :: "r"(dst), "l"(src));
}
#define CP_COMMIT() asm volatile("cp.async.commit_group;" ::: "memory")
#define CP_WAIT1()  asm volatile("cp.async.wait_group 1;" ::: "memory")
#define CP_WAIT0()  asm volatile("cp.async.wait_group 0;" ::: "memory")

__device__ __forceinline__ void mma_tf32(float (&c)[4], const uint4& a,
                                         uint32_t b0, uint32_t b1) {
    asm volatile(
        "mma.sync.aligned.m16n8k8.row.col.f32.tf32.tf32.f32 "
        "{%0,%1,%2,%3}, {%4,%5,%6,%7}, {%8,%9}, {%0,%1,%2,%3};"
        : "+f"(c[0]), "+f"(c[1]), "+f"(c[2]), "+f"(c[3])
        : "r"(a.x), "r"(a.y), "r"(a.z), "r"(a.w), "r"(b0), "r"(b1));
}
__device__ __forceinline__ float sigf(float x) { return 1.f / (1.f + __expf(-x)); }

// ---------------------------------------------------------------------------
// Init: zero h (both parities) and c
// ---------------------------------------------------------------------------
__global__ void init_state_kernel() {
    size_t i = (size_t)blockIdx.x * blockDim.x + threadIdx.x;
    const size_t n = (size_t)4 * NSEQ * HIDc;
    if (i < n) {
        ((uint32_t*)g_h)[i]     = 0u;
        ((uint32_t*)g_h)[n + i] = 0u;
        ((float*)g_c)[i]        = 0.f;
    }
}

// ---------------------------------------------------------------------------
// Pre-pass: features -> tf32 A-fragment layout.
// Per 128(M)x32(K) chunk: [wm(4)][k8(4)][mt(2)][lane(32)][e(4)] = 1024 uint4.
// g_x: [orient(2)][mtile(144)][chunk(24)][1024 uint4]
// ---------------------------------------------------------------------------
__global__ void convert_x_frag(const float* __restrict__ feat) {
    size_t i = (size_t)blockIdx.x * blockDim.x + threadIdx.x;
    const size_t per_orient = (size_t)144 * 24 * 1024;
    if (i >= 2 * per_orient) return;
    int orient = (int)(i / per_orient);
    size_t r = i - (size_t)orient * per_orient;
    int mtile = (int)(r / (24 * 1024));
    int chunk = (int)((r >> 10) % 24);
    int u     = (int)(r & 1023);
    int wm = u >> 8, k8 = (u >> 6) & 3, mt = (u >> 5) & 1, lane = u & 31;
    int row = mtile * 128 + wm * 32 + mt * 16 + (lane >> 2);
    int col = chunk * 32 + k8 * 8 + (lane & 3);

    float v[4];
#pragma unroll
    for (int e = 0; e < 4; e++) {
        int m = row + 8 * (e & 1);
        int k = col + 4 * (e >> 1);
        int rf;
        if (!orient) {
            rf = m;
        } else {
            int t  = m % 24;
            int nn = m / 24;
            int wg = nn % 24;
            int b  = nn / 24;
            rf = b * 576 + t * 24 + wg;
        }
        v[e] = feat[(size_t)rf * Dc + k];
    }
    *(uint4*)(g_x + i * 4) = make_uint4(f2tf32(v[0]), f2tf32(v[1]), f2tf32(v[2]), f2tf32(v[3]));
}

// ---------------------------------------------------------------------------
// Pre-pass: Wx -> tf32 B-fragment layout.
// Per 32(K)x128(N) chunk: [wn(2)][k8(4)][pp(4)][lane(32)][w(4)] = 1024 uint4.
// w: nt = pp*2 + (w>>1), b_word = w&1 (k offset +4 for b1).
// g_wx: [dir(4)][ntile(12)][chunk(24)][1024 uint4]
// ---------------------------------------------------------------------------
__global__ void convert_wx_frag(const float* __restrict__ w0, const float* __restrict__ w1,
                                const float* __restrict__ w2, const float* __restrict__ w3) {
    size_t i = (size_t)blockIdx.x * blockDim.x + threadIdx.x;
    const size_t per_dir = (size_t)12 * 24 * 1024;
    if (i >= 4 * per_dir) return;
    int dir = (int)(i / per_dir);
    const float* W = (dir == 0) ? w0 : (dir == 1) ? w1 : (dir == 2) ? w2 : w3;
    size_t r = i - (size_t)dir * per_dir;
    int ntile = (int)(r / (24 * 1024));
    int chunk = (int)((r >> 10) % 24);
    int u     = (int)(r & 1023);
    int wn = u >> 9, k8 = (u >> 7) & 3, pp = (u >> 5) & 3, lane = u & 31;

    uint32_t v[4];
#pragma unroll
    for (int w = 0; w < 4; w++) {
        int nt = pp * 2 + (w >> 1);
        int bw = w & 1;
        int n = ntile * 128 + wn * 64 + nt * 8 + (lane >> 2);
        int k = chunk * 32 + k8 * 8 + bw * 4 + (lane & 3);
        v[w] = f2tf32(W[(size_t)k * G4c + n]);
    }
    *(uint4*)(g_wx + i * 4) = make_uint4(v[0], v[1], v[2], v[3]);
}

// ---------------------------------------------------------------------------
// Pre-pass: Wh -> tf32 B-fragment layout.
// Per 32(K)x256(N: 4 gates x 64 cols) chunk:
// [wn(4)][k8(4)][g(4)][lane(32)][w(4)] = 2048 uint4; w: nt = w>>1, b_word = w&1.
// g_wh: [dir(4)][ctile(6)][chunk(12)][2048 uint4]
// ---------------------------------------------------------------------------
__global__ void convert_wh_frag(const float* __restrict__ w0, const float* __restrict__ w1,
                                const float* __restrict__ w2, const float* __restrict__ w3) {
    size_t i = (size_t)blockIdx.x * blockDim.x + threadIdx.x;
    const size_t per_dir = (size_t)6 * 12 * 2048;
    if (i >= 4 * per_dir) return;
    int dir = (int)(i / per_dir);
    const float* W = (dir == 0) ? w0 : (dir == 1) ? w1 : (dir == 2) ? w2 : w3;
    size_t r = i - (size_t)dir * per_dir;
    int ctile = (int)(r / (12 * 2048));
    int chunk = (int)((r >> 11) % 12);
    int u     = (int)(r & 2047);
    int wn = u >> 9, k8 = (u >> 7) & 3, g = (u >> 5) & 3, lane = u & 31;

    uint32_t v[4];
#pragma unroll
    for (int w = 0; w < 4; w++) {
        int nt = w >> 1;
        int bw = w & 1;
        int j = ctile * 64 + wn * 16 + nt * 8 + (lane >> 2);
        int k = chunk * 32 + k8 * 8 + bw * 4 + (lane & 3);
        v[w] = f2tf32(W[(size_t)k * G4c + g * HIDc + j]);
    }
    *(uint4*)(g_wh + i * 4) = make_uint4(v[0], v[1], v[2], v[3]);
}

// h fragment offset (words) within one dir's state array.
// Layout: [ntile(12)][chunk(12)][ (((wm*4+k8)*2+mt)*32+lane)*4 + e ]
__device__ __forceinline__ size_t h_frag_off(int n, int j) {
    int ntile = n >> 6, rn = n & 63, chunk = j >> 5, kk = j & 31;
    int wm = rn >> 5, mt = (rn >> 4) & 1, lane_q = rn & 7, e_row = (rn >> 3) & 1;
    int k8 = kk >> 3, lane_r = kk & 3, e_col = (kk >> 2) & 1;
    int e = e_col * 2 + e_row;
    int lane = lane_q * 4 + lane_r;
    return (size_t)(ntile * 12 + chunk) * 2048 + (size_t)((((wm * 4 + k8) * 2 + mt) * 32 + lane) * 4 + e);
}

// ---------------------------------------------------------------------------
// Phase 1: z = x @ Wx + b. Fragment-native, cp.async 2-stage.
// CTA 128x128, K=768 in 24 chunks of 32. 8 warps = 4(M) x 2(N).
// SMEM: 2 x (4096 + 4096) words = 64KB.
// ---------------------------------------------------------------------------
#define A1SZ 4096
#define B1SZ 4096

__global__ __launch_bounds__(256, 2)
void gemm_z_mma(const float* __restrict__ bhf, const float* __restrict__ bhb,
                const float* __restrict__ bvf, const float* __restrict__ bvb) {
    extern __shared__ uint32_t sm1[];
    const uint32_t sbase = smem_u32(sm1);

    const int tid  = threadIdx.x;
    const int lane = tid & 31;
    const int wid  = tid >> 5;
    const int wm   = wid & 3;
    const int wn   = wid >> 2;

    const int bx = blockIdx.x;        // 0..23
    const int by = blockIdx.y;        // 0..143
    const int orient = blockIdx.z;

    const int gc0  = bx * 128;
    const int half = (gc0 >= G4c) ? 1 : 0;
    const int wc0  = gc0 - half * G4c;
    const int dir  = orient * 2 + half;
    const int ntile = bx - half * 12;
    const float* bias = (orient == 0) ? (half ? bhb : bhf) : (half ? bvb : bvf);
    const int m0 = by * 128;

    const uint32_t* asrc = g_x + (size_t)(orient * 144 + by) * 24 * A1SZ + tid * 4;
    const uint32_t* bsrc = g_wx + ((size_t)dir * 12 + ntile) * 24 * B1SZ + tid * 4;

    float acc[2][8][4];
#pragma unroll
    for (int mt = 0; mt < 2; mt++)
#pragma unroll
        for (int nt = 0; nt < 8; nt++)
#pragma unroll
            for (int e = 0; e < 4; e++) acc[mt][nt][e] = 0.f;

#define LOAD1(c, buf) do {                                                   \
    const uint32_t* as_ = asrc + (size_t)(c) * A1SZ;                         \
    const uint32_t* bs_ = bsrc + (size_t)(c) * B1SZ;                         \
    uint32_t ao = sbase + ((buf) * A1SZ + tid * 4) * 4;                      \
    uint32_t bo = sbase + ((2 * A1SZ + (buf) * B1SZ) + tid * 4) * 4;         \
    _Pragma("unroll")                                                        \
    for (int q = 0; q < 4; q++) cp16(ao + q * 4096, as_ + q * 1024);         \
    _Pragma("unroll")                                                        \
    for (int q = 0; q < 4; q++) cp16(bo + q * 4096, bs_ + q * 1024);         \
    CP_COMMIT();                                                             \
} while (0)

    LOAD1(0, 0);
    for (int c = 0; c < 24; c++) {
        const int buf = c & 1;
        if (c + 1 < 24) { LOAD1(c + 1, buf ^ 1); CP_WAIT1(); }
        else            { CP_WAIT0(); }
        __syncthreads();

        const uint4* A4 = (const uint4*)(sm1 + buf * A1SZ);
        const uint4* B4 = (const uint4*)(sm1 + 2 * A1SZ + buf * B1SZ);
#pragma unroll
        for (int k8 = 0; k8 < 4; k8++) {
            uint4 a0 = A4[((wm * 4 + k8) * 2 + 0) * 32 + lane];
            uint4 a1 = A4[((wm * 4 + k8) * 2 + 1) * 32 + lane];
#pragma unroll
            for (int pp = 0; pp < 4; pp++) {
                uint4 b = B4[((wn * 4 + k8) * 4 + pp) * 32 + lane];
                mma_tf32(acc[0][2 * pp],     a0, b.x, b.y);
                mma_tf32(acc[1][2 * pp],     a1, b.x, b.y);
                mma_tf32(acc[0][2 * pp + 1], a0, b.z, b.w);
                mma_tf32(acc[1][2 * pp + 1], a1, b.z, b.w);
            }
        }
        __syncthreads();
    }
#undef LOAD1

    // Epilogue
    float* Zt = g_z + (size_t)dir * MTOT * G4c;
#pragma unroll
    for (int mt = 0; mt < 2; mt++) {
        int r = m0 + wm * 32 + mt * 16 + (lane >> 2);
#pragma unroll
        for (int nt = 0; nt < 8; nt++) {
            int c = wc0 + wn * 64 + nt * 8 + 2 * (lane & 3);
            float bv0 = __ldg(&bias[c]);
            float bv1 = __ldg(&bias[c + 1]);
            float2 v0 = make_float2(acc[mt][nt][0] + bv0, acc[mt][nt][1] + bv1);
            float2 v1 = make_float2(acc[mt][nt][2] + bv0, acc[mt][nt][3] + bv1);
            *(float2*)&Zt[(size_t)r * G4c + c]       = v0;
            *(float2*)&Zt[(size_t)(r + 8) * G4c + c] = v1;
        }
    }
}

// ---------------------------------------------------------------------------
// Phase 2: one LSTM step. Fragment-native, cp.async 2-stage.
// CTA: 64 seqs x (4 gates x 64 cols), K=384 in 12 chunks of 32.
// 8 warps = 2(M) x 4(N). SMEM: 2 x (2048 + 8192) words = 80KB.
// ---------------------------------------------------------------------------
#define A2SZ 2048
#define B2SZ 8192

__global__ __launch_bounds__(256, 2)
void lstm_step_mma(float* __restrict__ out, int s, int parity) {
    extern __shared__ uint32_t sm2[];
    const uint32_t sbase = smem_u32(sm2);

    const int dir = blockIdx.z;
    const bool forward = (dir == 0) || (dir == 2);
    const int t = forward ? s : (Tc - 1 - s);

    const int c0 = blockIdx.x * 64;   // ctile = blockIdx.x
    const int n0 = blockIdx.y * 64;   // ntile = blockIdx.y

    const uint32_t* hprev = g_h[parity][dir];
    uint32_t*       hnext = g_h[parity ^ 1][dir];
    float*          cst   = g_c[dir];
    const float*    Z     = g_z + (size_t)dir * MTOT * G4c;

    const int tid  = threadIdx.x;
    const int lane = tid & 31;
    const int wid  = tid >> 5;
    const int wm   = wid & 1;
    const int wn   = wid >> 1;

    const uint32_t* hsrc = hprev + (size_t)blockIdx.y * 12 * A2SZ + tid * 4;
    const uint32_t* wsrc = g_wh + ((size_t)dir * 6 + blockIdx.x) * 12 * B2SZ + tid * 4;

    float acc[2][4][2][4];
#pragma unroll
    for (int mt = 0; mt < 2; mt++)
#pragma unroll
        for (int g = 0; g < 4; g++)
#pragma unroll
            for (int nt = 0; nt < 2; nt++)
#pragma unroll
                for (int e = 0; e < 4; e++) acc[mt][g][nt][e] = 0.f;

#define LOAD2(c, buf) do {                                                   \
    const uint32_t* hs_ = hsrc + (size_t)(c) * A2SZ;                         \
    const uint32_t* ws_ = wsrc + (size_t)(c) * B2SZ;                         \
    uint32_t ho = sbase + ((buf) * A2SZ + tid * 4) * 4;                      \
    uint32_t wo = sbase + ((2 * A2SZ + (buf) * B2SZ) + tid * 4) * 4;         \
    _Pragma("unroll")                                                        \
    for (int q = 0; q < 2; q++) cp16(ho + q * 4096, hs_ + q * 1024);         \
    _Pragma("unroll")                                                        \
    for (int q = 0; q < 8; q++) cp16(wo + q * 4096, ws_ + q * 1024);         \
    CP_COMMIT();                                                             \
} while (0)

    LOAD2(0, 0);
    for (int c = 0; c < 12; c++) {
        const int buf = c & 1;
        if (c + 1 < 12) { LOAD2(c + 1, buf ^ 1); CP_WAIT1(); }
        else            { CP_WAIT0(); }
        __syncthreads();

        const uint4* H4 = (const uint4*)(sm2 + buf * A2SZ);
        const uint4* W4 = (const uint4*)(sm2 + 2 * A2SZ + buf * B2SZ);
#pragma unroll
        for (int k8 = 0; k8 < 4; k8++) {
            uint4 a0 = H4[((wm * 4 + k8) * 2 + 0) * 32 + lane];
            uint4 a1 = H4[((wm * 4 + k8) * 2 + 1) * 32 + lane];
#pragma unroll
            for (int g = 0; g < 4; g++) {
                uint4 b = W4[((wn * 4 + k8) * 4 + g) * 32 + lane];
                mma_tf32(acc[0][g][0], a0, b.x, b.y);
                mma_tf32(acc[1][g][0], a1, b.x, b.y);
                mma_tf32(acc[0][g][1], a0, b.z, b.w);
                mma_tf32(acc[1][g][1], a1, b.z, b.w);
            }
        }
        __syncthreads();
    }
#undef LOAD2

    // Epilogue: gates + state update + outputs
#pragma unroll
    for (int mt = 0; mt < 2; mt++) {
        int rbase = n0 + wm * 32 + mt * 16 + (lane >> 2);
#pragma unroll
        for (int nt = 0; nt < 2; nt++) {
            int j = c0 + wn * 16 + nt * 8 + 2 * (lane & 3);
#pragma unroll
            for (int hh = 0; hh < 2; hh++) {
                int n = rbase + 8 * hh;
                int e0 = 2 * hh;
                size_t zb = ((size_t)n * Tc + t) * G4c + j;
                float2 zi = *(const float2*)&Z[zb];
                float2 zf = *(const float2*)&Z[zb + HIDc];
                float2 zg = *(const float2*)&Z[zb + 2 * HIDc];
                float2 zo = *(const float2*)&Z[zb + 3 * HIDc];

                float gi0 = acc[mt][0][nt][e0]     + zi.x;
                float gi1 = acc[mt][0][nt][e0 + 1] + zi.y;
                float gf0 = acc[mt][1][nt][e0]     + zf.x;
                float gf1 = acc[mt][1][nt][e0 + 1] + zf.y;
                float gg0 = acc[mt][2][nt][e0]     + zg.x;
                float gg1 = acc[mt][2][nt][e0 + 1] + zg.y;
                float go0 = acc[mt][3][nt][e0]     + zo.x;
                float go1 = acc[mt][3][nt][e0 + 1] + zo.y;

                size_t sidx = (size_t)n * HIDc + j;
                float2 cold = *(const float2*)&cst[sidx];
                float cn0 = sigf(gf0) * cold.x + sigf(gi0) * tanhf(gg0);
                float cn1 = sigf(gf1) * cold.y + sigf(gi1) * tanhf(gg1);
                *(float2*)&cst[sidx] = make_float2(cn0, cn1);

                float hn0 = sigf(go0) * tanhf(cn0);
                float hn1 = sigf(go1) * tanhf(cn1);

                hnext[h_frag_off(n, j)]     = f2tf32(hn0);
                hnext[h_frag_off(n, j + 1)] = f2tf32(hn1);

                size_t orow;
                if (dir < 2) {
                    orow = (size_t)n * WGc + t;
                } else {
                    int b  = n / WGc;
                    int wg = n % WGc;
                    orow = (size_t)b * (HGc * WGc) + (size_t)t * WGc + wg;
                }
                *(float2*)&out[orow * 1536 + (size_t)dir * HIDc + j] = make_float2(hn0, hn1);
            }
        }
    }
}

// ---------------------------------------------------------------------------
// Launch
// ---------------------------------------------------------------------------
extern "C" void kernel_launch(void* const* d_in, const int* in_sizes, int n_in,
                              void* d_out, int out_size) {
    const float* features = (const float*)d_in[0];
    const float* hf_Wx = (const float*)d_in[1];
    const float* hf_Wh = (const float*)d_in[2];
    const float* hf_b  = (const float*)d_in[3];
    const float* hb_Wx = (const float*)d_in[4];
    const float* hb_Wh = (const float*)d_in[5];
    const float* hb_b  = (const float*)d_in[6];
    const float* vf_Wx = (const float*)d_in[7];
    const float* vf_Wh = (const float*)d_in[8];
    const float* vf_b  = (const float*)d_in[9];
    const float* vb_Wx = (const float*)d_in[10];
    const float* vb_Wh = (const float*)d_in[11];
    const float* vb_b  = (const float*)d_in[12];
    float* out = (float*)d_out;

    const int smem1 = 2 * (A1SZ + B1SZ) * 4;   // 65536
    const int smem2 = 2 * (A2SZ + B2SZ) * 4;   // 81920
    cudaFuncSetAttribute(gemm_z_mma,    cudaFuncAttributeMaxDynamicSharedMemorySize, smem1);
    cudaFuncSetAttribute(lstm_step_mma, cudaFuncAttributeMaxDynamicSharedMemorySize, smem2);

    // init states
    {
        size_t n = (size_t)4 * NSEQ * HIDc;
        init_state_kernel<<<(int)((n + 255) / 256), 256>>>();
    }
    // pre-convert to fragment-native tf32 layouts
    {
        size_t nx = (size_t)2 * 144 * 24 * 1024;
        convert_x_frag<<<(int)((nx + 255) / 256), 256>>>(features);
        size_t nwx = (size_t)4 * 12 * 24 * 1024;
        convert_wx_frag<<<(int)((nwx + 255) / 256), 256>>>(hf_Wx, hb_Wx, vf_Wx, vb_Wx);
        size_t nwh = (size_t)4 * 6 * 12 * 2048;
        convert_wh_frag<<<(int)((nwh + 255) / 256), 256>>>(hf_Wh, hb_Wh, vf_Wh, vb_Wh);
    }
    // Phase 1
    {
        dim3 grid(3072 / 128, MTOT / 128, 2);
        gemm_z_mma<<<grid, 256, smem1>>>(hf_b, hb_b, vf_b, vb_b);
    }
    // Phase 2
    {
        dim3 grid(HIDc / 64, NSEQ / 64, 4);
        for (int s = 0; s < Tc; s++) {
            lstm_step_mma<<<grid, 256, smem2>>>(out, s, s & 1);
        }
    }
}